// round 15
// baseline (speedup 1.0000x reference)
#include <cuda_runtime.h>
#include <cuda_bf16.h>

// CTC forward, LINEAR domain, per-thread exponent scaling, WARP-SPECIALIZED,
// PACKED f32x2 lattice arithmetic.
// One block (128 threads) per batch element:
//   warp 0     = consumer: lattice recurrence (LDS ratios + shfl + f32x2 FMA).
//   warps 1..3 = producers: emission ratios (LDG + ex2) into a double-buffered
//                smem ring; each handles 16 of every 48 steps, incl. the final
//                partial chunk (time clamped) -> consumer never touches gmem.
// One __syncthreads per 48 steps. Delayed renorm every 4 steps
// (measure j%4==1, apply j%4==3; exact power-of-2, bound ~2^84 < 2^127).

#define LOG2E 1.4426950408889634f
#define LN2   0.6931471805599453f
#define FULLM 0xffffffffu
#define MAXB  4096
#define CH    48
#define PSH   16     // steps per producer per chunk

__device__ float        g_per_ex[MAXB];
__device__ unsigned int g_count = 0;

typedef unsigned long long u64;

__device__ __forceinline__ float ex2f_(float x){ float r; asm("ex2.approx.f32 %0,%1;" : "=f"(r) : "f"(x)); return r; }
__device__ __forceinline__ float lg2f_(float x){ float r; asm("lg2.approx.f32 %0,%1;" : "=f"(r) : "f"(x)); return r; }

__device__ __forceinline__ u64  PK2(float lo, float hi){ u64 r; asm("mov.b64 %0,{%1,%2};" : "=l"(r) : "f"(lo), "f"(hi)); return r; }
__device__ __forceinline__ void UPK(u64 v, float& lo, float& hi){ asm("mov.b64 {%0,%1},%2;" : "=f"(lo), "=f"(hi) : "l"(v)); }
__device__ __forceinline__ u64  ADD2(u64 a, u64 b){ u64 r; asm("add.rn.f32x2 %0,%1,%2;" : "=l"(r) : "l"(a), "l"(b)); return r; }
__device__ __forceinline__ u64  MUL2(u64 a, u64 b){ u64 r; asm("mul.rn.f32x2 %0,%1,%2;" : "=l"(r) : "l"(a), "l"(b)); return r; }
__device__ __forceinline__ u64  FMA2(u64 a, u64 b, u64 c){ u64 r; asm("fma.rn.f32x2 %0,%1,%2,%3;" : "=l"(r) : "l"(a), "l"(b), "l"(c)); return r; }

__global__ __launch_bounds__(128, 1)
void ctc_forward_kernel(const float* __restrict__ pred,           // (B, T, C)
                        const int*   __restrict__ targets,        // (B, L)
                        const int*   __restrict__ pred_lengths,   // (B,)
                        const int*   __restrict__ target_lengths, // (B,)
                        float*       __restrict__ out,
                        int T, int C, int L, int B)
{
    extern __shared__ float4 ring[];       // [2][CH][32] = 48 KB dynamic
    __shared__ float sE[129];
    __shared__ float sO[128];
    __shared__ int   sExp[32];
    __shared__ float s_eb[3];
    __shared__ unsigned int s_last;

    const int b   = blockIdx.x;
    const int tid = threadIdx.x;
    const int wid = tid >> 5;              // 0 consumer, 1..3 producers
    const int wl  = tid & 31;
    const int p0  = wl * 4;

#define RING(buf, j, lane) ring[((buf) * CH + (j)) * 32 + (lane)]

    int   cols[4]; float skv[4], vm[4];
#pragma unroll
    for (int k = 0; k < 4; k++) {
        int p  = p0 + k;
        int li = (p < L) ? p : (L - 1);
        int l  = targets[(size_t)b * L + li];
        int pr = (li >= 1) ? targets[(size_t)b * L + li - 1] : -1;
        cols[k] = l;
        skv[k] = (l != 0 && l != pr) ? 1.f : 0.f;
        vm[k]  = (p < L) ? 1.f : 0.f;
    }
    const u64 SKa = PK2(skv[0], skv[1]);
    const u64 SKb = PK2(skv[2], skv[3]);

    const float* rowp = pred + (size_t)b * T * C;
    int pl = pred_lengths[b];
    int Teff = pl < T ? pl : T; if (Teff < 1) Teff = 1;
    const int steps = Teff - 1;            // updates at t = 1..steps
    const int fc    = steps / CH;          // full chunks
    const int rem   = steps - fc * CH;     // partial-chunk length
    const int nchAll = fc + (rem ? 1 : 0);

    // ---- consumer state (packed) ----
    u64 Oa = 0, Ob = 0, Ea = 0, Eb = 0;    // (0.f,0.f) packed
    float EX = 0.f;
    int   e_i = 0;
    float scale_in = (wl == 0) ? 0.f : 1.f;
    if (wid == 0 && wl == 0) {
        float eb0l2 = __ldg(rowp) * LOG2E;
        float o0 = ex2f_(fmaf(__ldg(rowp + cols[0]), LOG2E, -eb0l2)) * vm[0];
        Ea = PK2(1.f, 0.f);
        Oa = PK2(o0, 0.f);
    }
    float rn_sc = 1.f; int rn_ee = 0;      // delayed renorm state

#define STEP(R4)                                                             \
    {                                                                        \
        float o0, o1, o2, o3; UPK(Oa, o0, o1); UPK(Ob, o2, o3);              \
        float Om1 = __shfl_up_sync(FULLM, o3, 1) * scale_in;                 \
        u64 Sa = PK2(Om1, o0);                                               \
        u64 Sb = PK2(o1, o2);                                                \
        u64 Ra = PK2((R4).x, (R4).y);                                        \
        u64 Rb = PK2((R4).z, (R4).w);                                        \
        u64 ta = ADD2(Oa, Ea);                                               \
        u64 tb = ADD2(Ob, Eb);                                               \
        Oa = MUL2(FMA2(SKa, Sa, ta), Ra);                                    \
        Ob = MUL2(FMA2(SKb, Sb, tb), Rb);                                    \
        Ea = ADD2(Ea, Sa);                                                   \
        Eb = ADD2(Eb, Sb);                                                   \
        EX += o3;                                                            \
    }
#define MEASURE()                                                            \
    {                                                                        \
        float o0, o1, o2, o3, e0, e1, e2, e3;                                \
        UPK(Oa, o0, o1); UPK(Ob, o2, o3);                                    \
        UPK(Ea, e0, e1); UPK(Eb, e2, e3);                                    \
        float m = fmaxf(fmaxf(fmaxf(e0, e1), fmaxf(e2, e3)),                 \
                        fmaxf(fmaxf(o0, o1), fmaxf(o2, o3)));                \
        m = fmaxf(m, EX);                                                    \
        rn_ee = 0;                                                           \
        if (m > 0.f) rn_ee = (int)((__float_as_uint(m) >> 23) & 0xffu) - 127;\
        rn_sc = __uint_as_float((unsigned)(127 - rn_ee) << 23);              \
    }
#define APPLY()                                                              \
    {                                                                        \
        u64 SC = PK2(rn_sc, rn_sc);                                          \
        Oa = MUL2(Oa, SC); Ob = MUL2(Ob, SC);                                \
        Ea = MUL2(Ea, SC); Eb = MUL2(Eb, SC);                                \
        EX *= rn_sc;                                                         \
        e_i += rn_ee;                                                        \
        int ep = __shfl_up_sync(FULLM, e_i, 1);                              \
        int de = ep - e_i;                                                   \
        de = de > 126 ? 126 : (de < -126 ? -126 : de);                       \
        scale_in = (wl == 0) ? 0.f                                           \
                 : __uint_as_float((unsigned)(127 + de) << 23);              \
    }

    // ---- producer state: raw loads for share of chunk 0 ----
    float rb_[PSH], r0_[PSH], r1_[PSH], r2_[PSH], r3_[PSH];
    float pebs = 0.f;
    if (wid >= 1) {
        if (wid == 1) pebs = __ldg(rowp) * LOG2E;      // t = 0 blank term
#pragma unroll
        for (int jj = 0; jj < PSH; jj++) {
            int tt = (wid - 1) * PSH + jj + 1;
            int tc = tt > steps ? steps : tt;
            const float* pp = rowp + (size_t)tc * C;
            rb_[jj] = __ldg(pp);
            r0_[jj] = __ldg(pp + cols[0]);
            r1_[jj] = __ldg(pp + cols[1]);
            r2_[jj] = __ldg(pp + cols[2]);
            r3_[jj] = __ldg(pp + cols[3]);
        }
    }

    // ---- phase loop: producers fill chunk p, consumer eats chunk p-1 ----
    for (int p = 0; p <= nchAll; p++) {
        if (wid >= 1) {
            if (p < nchAll) {
#pragma unroll
                for (int jj = 0; jj < PSH; jj++) {
                    const int j = (wid - 1) * PSH + jj;
                    const int tglob = p * CH + j + 1;
                    float ebv = rb_[jj] * LOG2E;
                    float4 o;
                    o.x = ex2f_(fmaf(r0_[jj], LOG2E, -ebv)) * vm[0];
                    o.y = ex2f_(fmaf(r1_[jj], LOG2E, -ebv)) * vm[1];
                    o.z = ex2f_(fmaf(r2_[jj], LOG2E, -ebv)) * vm[2];
                    o.w = ex2f_(fmaf(r3_[jj], LOG2E, -ebv)) * vm[3];
                    RING(p & 1, j, wl) = o;
                    if (tglob <= steps) pebs += ebv;   // guard clamped dups
                }
#pragma unroll
                for (int jj = 0; jj < PSH; jj++) {     // preload chunk p+1 share
                    int tn = (p + 1) * CH + (wid - 1) * PSH + jj + 1;
                    if (tn > steps) tn = steps;
                    const float* pp = rowp + (size_t)tn * C;
                    rb_[jj] = __ldg(pp);
                    r0_[jj] = __ldg(pp + cols[0]);
                    r1_[jj] = __ldg(pp + cols[1]);
                    r2_[jj] = __ldg(pp + cols[2]);
                    r3_[jj] = __ldg(pp + cols[3]);
                }
            }
        } else if (p >= 1) {
            const int cidx = p - 1;
            const int buf  = cidx & 1;
            if (cidx < fc) {
#pragma unroll
                for (int j = 0; j < CH; j++) {
                    float4 r = RING(buf, j, wl);
                    STEP(r);
                    if ((j & 3) == 1) MEASURE();       // off-chain
                    if ((j & 3) == 3) APPLY();         // on-chain: 4 MUL2 + EX
                }
            } else {
                for (int j = 0; j < rem; j++) {        // partial last chunk
                    float4 r = RING(buf, j, wl);
                    STEP(r);
                    if ((j & 3) == 1) MEASURE();
                    if ((j & 3) == 3) APPLY();
                }
            }
        }
        __syncthreads();
    }
#undef STEP
#undef MEASURE
#undef APPLY

    // ---- gather + per-example loss ----
    if (wid == 0) {
        float o0, o1, o2, o3, e0, e1, e2, e3;
        UPK(Oa, o0, o1); UPK(Ob, o2, o3);
        UPK(Ea, e0, e1); UPK(Eb, e2, e3);
        sO[p0+0]=o0; sO[p0+1]=o1; sO[p0+2]=o2; sO[p0+3]=o3;
        sE[p0+0]=e0; sE[p0+1]=e1; sE[p0+2]=e2; sE[p0+3]=e3;
        if (wl == 31) sE[128] = EX;
        sExp[wl] = e_i;
    } else if (wl == 0) {
        s_eb[wid - 1] = pebs;
    }
    __syncthreads();

    if (tid == 0) {
        float ebsum = s_eb[0] + s_eb[1] + s_eb[2];
        int tl = target_lengths[b];
        int tlc = tl; if (tlc < 1) tlc = 1; if (tlc > L) tlc = L;
        float l1v = sO[tlc - 1];                       // state 2*tl - 1
        int   e1x = sExp[(tlc - 1) >> 2];
        float l2v = sE[tlc];                           // state 2*tl
        int   e2x = (tlc < 128) ? sExp[tlc >> 2] : sExp[31];
        float g1 = lg2f_(l1v) + (float)e1x;
        float g2 = lg2f_(l2v) + (float)e2x;
        float mm = fmaxf(g1, g2);
        float dd = fminf(g1, g2) - mm;
        float logv = mm + lg2f_(1.f + ex2f_(dd)) + ebsum;   // log2 P
        float per = -LN2 * logv;
        if (!(per < 1e29f)) per = 0.f;                 // zero_infinity (+inf/NaN)
        int den = tl < 1 ? 1 : tl;
        g_per_ex[b] = per / (float)den;
        __threadfence();
        unsigned pc = atomicAdd(&g_count, 1u);
        s_last = (pc == (unsigned)(B - 1)) ? 1u : 0u;
    }
    __syncthreads();

    // ---- last block computes the batch mean (deterministic fixed order) ----
    if (s_last && wid == 0) {
        float v = 0.f;
        for (int idx = wl; idx < B; idx += 32)
            v += *((volatile float*)&g_per_ex[idx]);
#pragma unroll
        for (int o = 16; o > 0; o >>= 1)
            v += __shfl_down_sync(FULLM, v, o);
        if (wl == 0) { out[0] = v / (float)B; g_count = 0u; }
    }
#undef RING
}

extern "C" void kernel_launch(void* const* d_in, const int* in_sizes, int n_in,
                              void* d_out, int out_size)
{
    const float* pred           = (const float*)d_in[0];
    const int*   targets        = (const int*)d_in[1];
    const int*   pred_lengths   = (const int*)d_in[2];
    const int*   target_lengths = (const int*)d_in[3];

    const int B = in_sizes[2];
    const int L = in_sizes[1] / B;
    const int C = 128;
    const int T = (in_sizes[0] / B) / C;

    const int ringBytes = 2 * CH * 32 * (int)sizeof(float4);   // 48 KB
    cudaFuncSetAttribute(ctc_forward_kernel,
                         cudaFuncAttributeMaxDynamicSharedMemorySize, ringBytes);

    ctc_forward_kernel<<<B, 128, ringBytes>>>(pred, targets, pred_lengths,
                                              target_lengths, (float*)d_out,
                                              T, C, L, B);
}